// round 6
// baseline (speedup 1.0000x reference)
#include <cuda_runtime.h>
#include <cuda_bf16.h>
#include <math.h>

// Problem constants
#define BATCH 8
#define MDIM 256
#define NDIM 256
#define DDIM 512
#define NDIAG 511            // M + N - 1
#define INFV 100000000.0f    // matches reference _INF
#define GAMMA_MIN 0.0001f

// ---------------------------------------------------------------------------
// Scratch (static device globals; no allocation)
// layout: diag-major  [b][d][i]  with i = row index (global m), d = m + n
// ---------------------------------------------------------------------------
__device__ float  g_rx[BATCH * MDIM];                 // 1/||x_m||
__device__ float  g_ry[BATCH * NDIM];                 // 1/||y_n||
__device__ float  g_cost[BATCH * NDIAG * MDIM];       // cost, diag-major
__device__ float  g_R[BATCH * NDIAG * MDIM];          // R (interior), diag-major
__device__ float  g_S[BATCH * NDIAG * MDIM];          // softmin value (= R - cost)
__device__ float4 g_W[BATCH * NDIAG * MDIM];          // (wd, wn, wr, 0) per cell
__device__ float  g_E[BATCH * NDIAG * MDIM];          // alignment, diag-major

__device__ __forceinline__ float clamp50(float v)
{
    return fminf(fmaxf(v, -50.0f), 50.0f);
}

// ---------------------------------------------------------------------------
// Kernel 1: inverse row norms for x and y.  One warp per row.
// ---------------------------------------------------------------------------
__global__ __launch_bounds__(256) void norms_kernel(const float* __restrict__ x,
                                                    const float* __restrict__ y)
{
    int warp = threadIdx.x >> 5;
    int lane = threadIdx.x & 31;
    int row  = blockIdx.x * 8 + warp;          // 512 blocks * 8 warps = 4096 rows

    const float* base;
    float* out;
    if (row < BATCH * MDIM) {
        base = x + (size_t)row * DDIM;
        out  = g_rx + row;
    } else {
        int r = row - BATCH * MDIM;
        base = y + (size_t)r * DDIM;
        out  = g_ry + r;
    }

    const float4* b4 = reinterpret_cast<const float4*>(base);
    float s = 0.0f;
#pragma unroll
    for (int t = 0; t < 4; ++t) {
        float4 v = b4[lane + 32 * t];          // 128 float4 per row
        s += v.x * v.x + v.y * v.y + v.z * v.z + v.w * v.w;
    }
#pragma unroll
    for (int o = 16; o; o >>= 1) s += __shfl_xor_sync(0xFFFFFFFFu, s, o);

    if (lane == 0) {
        float n = sqrtf(s);
        n = fmaxf(n, 1e-8f);
        *out = 1.0f / n;
    }
}

// ---------------------------------------------------------------------------
// Kernel 2: cost = 1 - (x.y) * rx * ry, written DIAG-MAJOR.
// Tiled SGEMM: 64x64 tile per block, BK=16, 256 threads, 4x4 microtile.
// ---------------------------------------------------------------------------
#define BM 64
#define BN 64
#define BK 16

__global__ __launch_bounds__(256) void cost_kernel(const float* __restrict__ x,
                                                   const float* __restrict__ y)
{
    __shared__ float Xs[BK][BM + 1];
    __shared__ float Ys[BK][BN + 1];

    int b  = blockIdx.z;
    int m0 = blockIdx.y * BM;
    int n0 = blockIdx.x * BN;
    int tx = threadIdx.x;      // 0..15
    int ty = threadIdx.y;      // 0..15
    int tid = ty * 16 + tx;

    const float* xb = x + ((size_t)b * MDIM + m0) * DDIM;
    const float* yb = y + ((size_t)b * NDIM + n0) * DDIM;

    float acc[4][4];
#pragma unroll
    for (int r = 0; r < 4; ++r)
#pragma unroll
        for (int c = 0; c < 4; ++c) acc[r][c] = 0.0f;

    int kk = tid & 15;
    int rr = tid >> 4;

    for (int k0 = 0; k0 < DDIM; k0 += BK) {
#pragma unroll
        for (int r = 0; r < 4; ++r) {
            Xs[kk][rr + r * 16] = xb[(size_t)(rr + r * 16) * DDIM + k0 + kk];
            Ys[kk][rr + r * 16] = yb[(size_t)(rr + r * 16) * DDIM + k0 + kk];
        }
        __syncthreads();
#pragma unroll
        for (int k = 0; k < BK; ++k) {
            float a[4], bv[4];
#pragma unroll
            for (int r = 0; r < 4; ++r) a[r]  = Xs[k][ty * 4 + r];
#pragma unroll
            for (int c = 0; c < 4; ++c) bv[c] = Ys[k][tx * 4 + c];
#pragma unroll
            for (int r = 0; r < 4; ++r)
#pragma unroll
                for (int c = 0; c < 4; ++c) acc[r][c] += a[r] * bv[c];
        }
        __syncthreads();
    }

    float* costb = g_cost + (size_t)b * NDIAG * MDIM;
#pragma unroll
    for (int r = 0; r < 4; ++r) {
        int row = m0 + ty * 4 + r;
        float rx = g_rx[b * MDIM + row];
#pragma unroll
        for (int c = 0; c < 4; ++c) {
            int col = n0 + tx * 4 + c;
            float ry = g_ry[b * NDIM + col];
            float v = 1.0f - acc[r][c] * rx * ry;
            costb[(size_t)(row + col) * MDIM + row] = v;   // diag-major
        }
    }
}

// ---------------------------------------------------------------------------
// Kernel 3: forward soft-DTW wavefront.  One block per batch, thread = row i.
// Writes R and softmin value S diag-major (coalesced) for the backward pass.
// ---------------------------------------------------------------------------
__global__ __launch_bounds__(256) void fwd_kernel(const float* __restrict__ gamma_ptr,
                                                  float* __restrict__ d_out)
{
    __shared__ float buf[3][MDIM];

    int b = blockIdx.x;
    int i = threadIdx.x;

    float gv = fmaxf(fabsf(*gamma_ptr), GAMMA_MIN);
    float ig = 1.0f / gv;

    const float* costb = g_cost + (size_t)b * NDIAG * MDIM;
    float* Rb = g_R + (size_t)b * NDIAG * MDIM;
    float* Sb = g_S + (size_t)b * NDIAG * MDIM;

    int pa = 0, pb = 1, pc = 2;            // pa = diag d-2, pb = diag d-1, pc = new

    // prefetch cost for d = 0
    float cnext = costb[i];

    for (int d = 0; d < NDIAG; ++d) {
        int j = d - i;
        bool valid = (j >= 0) && (j < NDIM);

        float cv = cnext;
        if (d + 1 < NDIAG) cnext = costb[(size_t)(d + 1) * MDIM + i];

        // three-way softmin with explicit boundary semantics
        float a  = (i > 0 && j > 0) ? buf[pa][i - 1]
                                    : ((i == 0 && j == 0) ? 0.0f : INFV);
        float bb = (i > 0) ? buf[pb][i - 1] : INFV;
        float cc = (j > 0) ? buf[pb][i]     : INFV;

        float mn = fminf(a, fminf(bb, cc));
        float s  = __expf((mn - a)  * ig)
                 + __expf((mn - bb) * ig)
                 + __expf((mn - cc) * ig);
        float Sv = mn - gv * __logf(s);
        float Rv = cv + Sv;

        if (valid) {
            buf[pc][i] = Rv;
            Rb[(size_t)d * MDIM + i] = Rv;
            Sb[(size_t)d * MDIM + i] = Sv;
            if (d == NDIAG - 1) {
                // only i = 255 is valid on the last diagonal: the distance
                d_out[BATCH * MDIM * NDIM + b] = Rv;
            }
        }
        __syncthreads();
        int t = pa; pa = pb; pb = pc; pc = t;
    }
}

// ---------------------------------------------------------------------------
// Kernel 4: precompute backward weights per cell (fully parallel).
//   wd = exp(clamp((S[i+1,j+1] - R[i,j]) / g))   (0 if neighbor invalid)
//   wn = exp(clamp((S[i+1,j  ] - R[i,j]) / g))
//   wr = exp(clamp((S[i  ,j+1] - R[i,j]) / g))
// Stored as float4 diag-major so bwd does one LDG.128 per cell.
// ---------------------------------------------------------------------------
__global__ __launch_bounds__(256) void weights_kernel(const float* __restrict__ gamma_ptr)
{
    int d = blockIdx.x;
    int b = blockIdx.y;
    int i = threadIdx.x;
    int j = d - i;

    float gv = fmaxf(fabsf(*gamma_ptr), GAMMA_MIN);
    float ig = 1.0f / gv;

    const float* Rb = g_R + (size_t)b * NDIAG * MDIM;
    const float* Sb = g_S + (size_t)b * NDIAG * MDIM;

    float4 w = make_float4(0.0f, 0.0f, 0.0f, 0.0f);
    if (j >= 0 && j < NDIM) {
        float rc = Rb[(size_t)d * MDIM + i];
        if (i + 1 < MDIM && j + 1 < NDIM)
            w.x = __expf(clamp50((Sb[(size_t)(d + 2) * MDIM + i + 1] - rc) * ig));
        if (i + 1 < MDIM)
            w.y = __expf(clamp50((Sb[(size_t)(d + 1) * MDIM + i + 1] - rc) * ig));
        if (j + 1 < NDIM)
            w.z = __expf(clamp50((Sb[(size_t)(d + 1) * MDIM + i] - rc) * ig));
    }
    g_W[((size_t)b * NDIAG + d) * MDIM + i] = w;
}

// ---------------------------------------------------------------------------
// Kernel 5: backward soft-DTW wavefront.  One block per batch, thread = row i.
// All loads are a single prefetched LDG.128 of precomputed weights (4-deep
// ring); stores are diag-major (coalesced).  Loop body: LDS + 2 FMA + STS +
// STG + BAR.
// ---------------------------------------------------------------------------
#define PF 4

__global__ __launch_bounds__(256) void bwd_kernel()
{
    __shared__ float E[3][MDIM];

    int b = blockIdx.x;
    int i = threadIdx.x;

    const float4* Wb = g_W + (size_t)b * NDIAG * MDIM;
    float* Eb = g_E + (size_t)b * NDIAG * MDIM;

    // diag 510 seed: only cell (255,255) is valid there, E = 1
    E[0][i] = 0.0f; E[1][i] = 0.0f; E[2][i] = 0.0f;
    if (i == MDIM - 1) {
        E[1][i] = 1.0f;
        Eb[(size_t)(NDIAG - 1) * MDIM + i] = 1.0f;
    }

    // prime the prefetch ring with diagonals 509..509-PF+1
    float4 wreg[PF];
#pragma unroll
    for (int p = 0; p < PF; ++p)
        wreg[p] = Wb[(size_t)(NDIAG - 2 - p) * MDIM + i];

    __syncthreads();

    int p2 = 0, p1 = 1, pc = 2;

    for (int d = NDIAG - 2; d >= 0; --d) {
        float4 w = wreg[0];
#pragma unroll
        for (int p = 0; p < PF - 1; ++p) wreg[p] = wreg[p + 1];
        int dn = d - PF;
        if (dn >= 0) wreg[PF - 1] = Wb[(size_t)dn * MDIM + i];

        float e2 = (i < MDIM - 1) ? E[p2][i + 1] : 0.0f;
        float en = (i < MDIM - 1) ? E[p1][i + 1] : 0.0f;
        float er = E[p1][i];

        float Ev = fmaf(e2, w.x, fmaf(en, w.y, er * w.z));

        int j = d - i;
        bool valid = (j >= 0) && (j < NDIM);
        float Eo = valid ? Ev : 0.0f;

        E[pc][i] = Eo;
        Eb[(size_t)d * MDIM + i] = Eo;     // coalesced diag-major store

        __syncthreads();
        int t = p2; p2 = p1; p1 = pc; pc = t;
    }
}

// ---------------------------------------------------------------------------
// Kernel 6: diag-major E -> row-major alignment output.  32x32 output tile
// per block.  Cell (i0+r, j0+c) lives at diag r+c, row-slot r within the
// staged segment: out = sm[r+c][r].  Padding to 33 makes the read pattern
// (bank = (2r + lane) mod 32) conflict-free.
// ---------------------------------------------------------------------------
__global__ __launch_bounds__(256) void transpose_kernel(float* __restrict__ out)
{
    __shared__ float sm[63][33];

    int b  = blockIdx.z;
    int i0 = blockIdx.y * 32;
    int j0 = blockIdx.x * 32;
    int d0 = i0 + j0;

    int lane = threadIdx.x & 31;
    int wy   = threadIdx.x >> 5;       // 0..7

    const float* Eb = g_E + (size_t)b * NDIAG * MDIM;

    // load 63 diagonal segments of 32 consecutive row-slots (coalesced)
    for (int dl = wy; dl < 63; dl += 8)
        sm[dl][lane] = Eb[(size_t)(d0 + dl) * MDIM + i0 + lane];
    __syncthreads();

    float* outb = out + (size_t)b * MDIM * NDIM;
#pragma unroll
    for (int r = wy; r < 32; r += 8)   // row i = i0 + r, col j = j0 + lane
        outb[(size_t)(i0 + r) * NDIM + j0 + lane] = sm[r + lane][r];
}

// ---------------------------------------------------------------------------
// Launch.  Inputs: x [8,256,512] f32, y [8,256,512] f32, gamma [] f32.
// Output: alignment [8,256,256] then distance [8], f32.
// ---------------------------------------------------------------------------
extern "C" void kernel_launch(void* const* d_in, const int* in_sizes, int n_in,
                              void* d_out, int out_size)
{
    const float* x     = (const float*)d_in[0];
    const float* y     = (const float*)d_in[1];
    const float* gamma = (const float*)d_in[2];
    float* out = (float*)d_out;

    norms_kernel<<<512, 256>>>(x, y);
    cost_kernel<<<dim3(NDIM / BN, MDIM / BM, BATCH), dim3(16, 16)>>>(x, y);
    fwd_kernel<<<BATCH, 256>>>(gamma, out);
    weights_kernel<<<dim3(NDIAG, BATCH), 256>>>(gamma);
    bwd_kernel<<<BATCH, 256>>>();
    transpose_kernel<<<dim3(8, 8, BATCH), 256>>>(out);
}

// round 8
// speedup vs baseline: 2.1145x; 2.1145x over previous
#include <cuda_runtime.h>
#include <cuda_bf16.h>
#include <math.h>

// Problem constants
#define BATCH 8
#define MDIM 256
#define NDIM 256
#define DDIM 512
#define NDIAG 511            // M + N - 1
#define INFV 100000000.0f    // matches reference _INF
#define GAMMA_MIN 0.0001f

#define UNR 8                // prefetch depth / unroll factor (must divide 512)

// ---------------------------------------------------------------------------
// Scratch (static device globals; no allocation)
// layout: diag-major  [b][d][i]  with i = row index (global m), d = m + n
// ---------------------------------------------------------------------------
__device__ float  g_rx[BATCH * MDIM];                 // 1/||x_m||
__device__ float  g_ry[BATCH * NDIM];                 // 1/||y_n||
__device__ float  g_cost[BATCH * NDIAG * MDIM];       // cost, diag-major
__device__ float  g_R[BATCH * NDIAG * MDIM];          // R (interior), diag-major
__device__ float  g_S[BATCH * NDIAG * MDIM];          // softmin value (= R - cost)
__device__ float4 g_W[BATCH * NDIAG * MDIM];          // (wd, wn, wr, 0) per cell
__device__ float  g_E[BATCH * NDIAG * MDIM];          // alignment, diag-major

__device__ __forceinline__ float clamp50(float v)
{
    return fminf(fmaxf(v, -50.0f), 50.0f);
}

__device__ __forceinline__ float ex2_(float x)       // MUFU.EX2
{
    float r;
    asm("ex2.approx.f32 %0, %1;" : "=f"(r) : "f"(x));
    return r;
}
__device__ __forceinline__ float lg2_(float x)       // MUFU.LG2
{
    float r;
    asm("lg2.approx.f32 %0, %1;" : "=f"(r) : "f"(x));
    return r;
}

// ---------------------------------------------------------------------------
// Kernel 1: inverse row norms for x and y.  One warp per row.
// ---------------------------------------------------------------------------
__global__ __launch_bounds__(256) void norms_kernel(const float* __restrict__ x,
                                                    const float* __restrict__ y)
{
    int warp = threadIdx.x >> 5;
    int lane = threadIdx.x & 31;
    int row  = blockIdx.x * 8 + warp;          // 512 blocks * 8 warps = 4096 rows

    const float* base;
    float* out;
    if (row < BATCH * MDIM) {
        base = x + (size_t)row * DDIM;
        out  = g_rx + row;
    } else {
        int r = row - BATCH * MDIM;
        base = y + (size_t)r * DDIM;
        out  = g_ry + r;
    }

    const float4* b4 = reinterpret_cast<const float4*>(base);
    float s = 0.0f;
#pragma unroll
    for (int t = 0; t < 4; ++t) {
        float4 v = b4[lane + 32 * t];          // 128 float4 per row
        s += v.x * v.x + v.y * v.y + v.z * v.z + v.w * v.w;
    }
#pragma unroll
    for (int o = 16; o; o >>= 1) s += __shfl_xor_sync(0xFFFFFFFFu, s, o);

    if (lane == 0) {
        float n = sqrtf(s);
        n = fmaxf(n, 1e-8f);
        *out = 1.0f / n;
    }
}

// ---------------------------------------------------------------------------
// Kernel 2: cost = 1 - (x.y) * rx * ry, written DIAG-MAJOR.
// Tiled SGEMM: 64x64 tile per block, BK=16, 256 threads, 4x4 microtile.
// ---------------------------------------------------------------------------
#define BM 64
#define BN 64
#define BK 16

__global__ __launch_bounds__(256) void cost_kernel(const float* __restrict__ x,
                                                   const float* __restrict__ y)
{
    __shared__ float Xs[BK][BM + 1];
    __shared__ float Ys[BK][BN + 1];

    int b  = blockIdx.z;
    int m0 = blockIdx.y * BM;
    int n0 = blockIdx.x * BN;
    int tx = threadIdx.x;      // 0..15
    int ty = threadIdx.y;      // 0..15
    int tid = ty * 16 + tx;

    const float* xb = x + ((size_t)b * MDIM + m0) * DDIM;
    const float* yb = y + ((size_t)b * NDIM + n0) * DDIM;

    float acc[4][4];
#pragma unroll
    for (int r = 0; r < 4; ++r)
#pragma unroll
        for (int c = 0; c < 4; ++c) acc[r][c] = 0.0f;

    int kk = tid & 15;
    int rr = tid >> 4;

    for (int k0 = 0; k0 < DDIM; k0 += BK) {
#pragma unroll
        for (int r = 0; r < 4; ++r) {
            Xs[kk][rr + r * 16] = xb[(size_t)(rr + r * 16) * DDIM + k0 + kk];
            Ys[kk][rr + r * 16] = yb[(size_t)(rr + r * 16) * DDIM + k0 + kk];
        }
        __syncthreads();
#pragma unroll
        for (int k = 0; k < BK; ++k) {
            float a[4], bv[4];
#pragma unroll
            for (int r = 0; r < 4; ++r) a[r]  = Xs[k][ty * 4 + r];
#pragma unroll
            for (int c = 0; c < 4; ++c) bv[c] = Ys[k][tx * 4 + c];
#pragma unroll
            for (int r = 0; r < 4; ++r)
#pragma unroll
                for (int c = 0; c < 4; ++c) acc[r][c] += a[r] * bv[c];
        }
        __syncthreads();
    }

    float* costb = g_cost + (size_t)b * NDIAG * MDIM;
#pragma unroll
    for (int r = 0; r < 4; ++r) {
        int row = m0 + ty * 4 + r;
        float rx = g_rx[b * MDIM + row];
#pragma unroll
        for (int c = 0; c < 4; ++c) {
            int col = n0 + tx * 4 + c;
            float ry = g_ry[b * NDIM + col];
            float v = 1.0f - acc[r][c] * rx * ry;
            costb[(size_t)(row + col) * MDIM + row] = v;   // diag-major
        }
    }
}

// ---------------------------------------------------------------------------
// Kernel 3: forward soft-DTW wavefront.  One block per batch, thread = row i.
// 8-deep cost prefetch ring with STATIC slot indices (loop unrolled by 8, so
// slot == unroll position).  Shared diagonal buffers are a 4-slot modular
// ring (slot = d mod 4 == u mod 4, also static).  One barrier per diagonal.
// ---------------------------------------------------------------------------
__global__ __launch_bounds__(256) void fwd_kernel(const float* __restrict__ gamma_ptr,
                                                  float* __restrict__ d_out)
{
    __shared__ float buf[4][MDIM];

    int b = blockIdx.x;
    int i = threadIdx.x;

    float gv  = fmaxf(fabsf(*gamma_ptr), GAMMA_MIN);
    float ig2 = 1.4426950408889634f / gv;       // 1/(gv) * log2(e)
    float gl  = gv * 0.6931471805599453f;       // gv * ln(2)

    const float* costb = g_cost + (size_t)b * NDIAG * MDIM;
    float* Rb = g_R + (size_t)b * NDIAG * MDIM;
    float* Sb = g_S + (size_t)b * NDIAG * MDIM;

    // prime the prefetch ring with diagonals 0..UNR-1
    float creg[UNR];
#pragma unroll
    for (int u = 0; u < UNR; ++u)
        creg[u] = costb[(size_t)u * MDIM + i];

    for (int t = 0; t < 512; t += UNR) {
#pragma unroll
        for (int u = 0; u < UNR; ++u) {
            int d = t + u;
            int j = d - i;
            bool valid = (j >= 0) && (j < NDIM);

            float cv = creg[u];
            int dn = d + UNR;
            if (dn < NDIAG)                        // reload for iteration d+UNR
                creg[u] = costb[(size_t)dn * MDIM + i];

            // static smem slots: write d mod 4, read (d-1) mod 4, (d-2) mod 4
            const int sw = u & 3;
            const int s1 = (u + 3) & 3;
            const int s2 = (u + 2) & 3;

            float a  = (i > 0 && j > 0) ? buf[s2][i - 1]
                                        : ((i == 0 && j == 0) ? 0.0f : INFV);
            float bb = (i > 0) ? buf[s1][i - 1] : INFV;
            float cc = (j > 0) ? buf[s1][i]     : INFV;

            float mn = fminf(a, fminf(bb, cc));
            float s  = ex2_((mn - a)  * ig2)
                     + ex2_((mn - bb) * ig2)
                     + ex2_((mn - cc) * ig2);
            float Sv = mn - gl * lg2_(s);
            float Rv = cv + Sv;

            if (valid) {
                buf[sw][i] = Rv;
                Rb[(size_t)d * MDIM + i] = Rv;
                Sb[(size_t)d * MDIM + i] = Sv;
                if (d == NDIAG - 1)
                    d_out[BATCH * MDIM * NDIM + b] = Rv;   // distance (i==255)
            }
            __syncthreads();
        }
    }
}

// ---------------------------------------------------------------------------
// Kernel 4: precompute backward weights per cell (fully parallel).
//   wd = exp(clamp((S[i+1,j+1] - R[i,j]) / g))   (0 if neighbor invalid)
//   wn = exp(clamp((S[i+1,j  ] - R[i,j]) / g))
//   wr = exp(clamp((S[i  ,j+1] - R[i,j]) / g))
// Also 0 for invalid cells, so bwd needs NO validity logic at all.
// ---------------------------------------------------------------------------
__global__ __launch_bounds__(256) void weights_kernel(const float* __restrict__ gamma_ptr)
{
    int d = blockIdx.x;
    int b = blockIdx.y;
    int i = threadIdx.x;
    int j = d - i;

    float gv = fmaxf(fabsf(*gamma_ptr), GAMMA_MIN);
    float ig = 1.0f / gv;

    const float* Rb = g_R + (size_t)b * NDIAG * MDIM;
    const float* Sb = g_S + (size_t)b * NDIAG * MDIM;

    float4 w = make_float4(0.0f, 0.0f, 0.0f, 0.0f);
    if (j >= 0 && j < NDIM) {
        float rc = Rb[(size_t)d * MDIM + i];
        if (i + 1 < MDIM && j + 1 < NDIM)
            w.x = __expf(clamp50((Sb[(size_t)(d + 2) * MDIM + i + 1] - rc) * ig));
        if (i + 1 < MDIM)
            w.y = __expf(clamp50((Sb[(size_t)(d + 1) * MDIM + i + 1] - rc) * ig));
        if (j + 1 < NDIM)
            w.z = __expf(clamp50((Sb[(size_t)(d + 1) * MDIM + i] - rc) * ig));
    }
    g_W[((size_t)b * NDIAG + d) * MDIM + i] = w;
}

// ---------------------------------------------------------------------------
// Kernel 5: backward soft-DTW wavefront.  One block per batch, thread = row i.
// 8-deep LDG.128 weight prefetch ring with static slot indices; E diagonals
// in a 4-slot modular smem ring; coalesced diag-major stores.
// Body: LDS x3 + 2 FMA + STS + STG + BAR -- no long-scoreboard on the path.
// ---------------------------------------------------------------------------
__global__ __launch_bounds__(256) void bwd_kernel()
{
    __shared__ float E[4][MDIM];

    int b = blockIdx.x;
    int i = threadIdx.x;

    const float4* Wb = g_W + (size_t)b * NDIAG * MDIM;
    float* Eb = g_E + (size_t)b * NDIAG * MDIM;

    // diag 510 lives in slot 510 mod 4 = 2; diag 511 "virtual" slot 3 = zeros
    E[0][i] = 0.0f; E[1][i] = 0.0f; E[2][i] = 0.0f; E[3][i] = 0.0f;
    if (i == MDIM - 1) E[2][i] = 1.0f;
    Eb[(size_t)(NDIAG - 1) * MDIM + i] = (i == MDIM - 1) ? 1.0f : 0.0f;

    // prime the ring: slot u holds weights for diag 509-u
    float4 wreg[UNR];
#pragma unroll
    for (int u = 0; u < UNR; ++u)
        wreg[u] = Wb[(size_t)(NDIAG - 2 - u) * MDIM + i];

    __syncthreads();

    for (int t = 0; t < 512; t += UNR) {
#pragma unroll
        for (int u = 0; u < UNR; ++u) {
            int d = NDIAG - 2 - (t + u);          // 509 down to -2

            float4 w = wreg[u];
            int dn = d - UNR;
            if (dn >= 0)                           // reload for iteration d-UNR
                wreg[u] = Wb[(size_t)dn * MDIM + i];

            // smem slots: write d mod 4, read (d+1) mod 4, (d+2) mod 4
            // d mod 4 == (509 - u) mod 4 == (1 - u) mod 4  (t multiple of 8)
            const int sw = (513 - u) & 3;          // d     mod 4
            const int s1 = (514 - u) & 3;          // (d+1) mod 4
            const int s2 = (515 - u) & 3;          // (d+2) mod 4

            float e2 = (i < MDIM - 1) ? E[s2][i + 1] : 0.0f;
            float en = (i < MDIM - 1) ? E[s1][i + 1] : 0.0f;
            float er = E[s1][i];

            float Ev = fmaf(e2, w.x, fmaf(en, w.y, er * w.z));

            E[sw][i] = Ev;                         // weights are 0 off-matrix
            if (d >= 0)
                Eb[(size_t)d * MDIM + i] = Ev;     // coalesced diag-major store

            __syncthreads();
        }
    }
}

// ---------------------------------------------------------------------------
// Kernel 6: diag-major E -> row-major alignment output.  32x32 output tile
// per block.  Cell (i0+r, j0+c) lives at diag r+c, row-slot r: sm[r+c][r].
// Pad to 33 so the read pattern (bank = (2r + lane) mod 32) is conflict-free.
// ---------------------------------------------------------------------------
__global__ __launch_bounds__(256) void transpose_kernel(float* __restrict__ out)
{
    __shared__ float sm[63][33];

    int b  = blockIdx.z;
    int i0 = blockIdx.y * 32;
    int j0 = blockIdx.x * 32;
    int d0 = i0 + j0;

    int lane = threadIdx.x & 31;
    int wy   = threadIdx.x >> 5;       // 0..7

    const float* Eb = g_E + (size_t)b * NDIAG * MDIM;

    // load 63 diagonal segments of 32 consecutive row-slots (coalesced)
    for (int dl = wy; dl < 63; dl += 8)
        sm[dl][lane] = Eb[(size_t)(d0 + dl) * MDIM + i0 + lane];
    __syncthreads();

    float* outb = out + (size_t)b * MDIM * NDIM;
#pragma unroll
    for (int r = wy; r < 32; r += 8)   // row i = i0 + r, col j = j0 + lane
        outb[(size_t)(i0 + r) * NDIM + j0 + lane] = sm[r + lane][r];
}

// ---------------------------------------------------------------------------
// Launch.  Inputs: x [8,256,512] f32, y [8,256,512] f32, gamma [] f32.
// Output: alignment [8,256,256] then distance [8], f32.
// ---------------------------------------------------------------------------
extern "C" void kernel_launch(void* const* d_in, const int* in_sizes, int n_in,
                              void* d_out, int out_size)
{
    const float* x     = (const float*)d_in[0];
    const float* y     = (const float*)d_in[1];
    const float* gamma = (const float*)d_in[2];
    float* out = (float*)d_out;

    norms_kernel<<<512, 256>>>(x, y);
    cost_kernel<<<dim3(NDIM / BN, MDIM / BM, BATCH), dim3(16, 16)>>>(x, y);
    fwd_kernel<<<BATCH, 256>>>(gamma, out);
    weights_kernel<<<dim3(NDIAG, BATCH), 256>>>(gamma);
    bwd_kernel<<<BATCH, 256>>>();
    transpose_kernel<<<dim3(8, 8, BATCH), 256>>>(out);
}